// round 13
// baseline (speedup 1.0000x reference)
#include <cuda_runtime.h>

// Bilinear_3882650435896: conv_transpose2d(x, w, stride=2) with block-diagonal
// w (per-channel bilinear filter) == depthwise 2x upsample.
// x: (4,256,128,128) f32 -> out: (4,256,258,258) f32.
//
// R12 -> R13: persistent CTAs + double-buffered staging. Each CTA loops over
// tiles (t += gridDim.x). Per iteration: issue next tile's LDGs into regs,
// compute+store the current tile from smem (R11's dense-STG body — this
// overlaps the LDG latency with store work), then STS the prefetch into the
// spare buffer and sync once. Store stream stays continuous: no per-tile
// staging stall, no wave-transition bubbles.

#define C      256
#define HIN    128
#define HOUT   258
#define NROWS  18        // input rows staged per tile (R-1 .. R+16)
#define SROW   136       // smem row: 4 left-pad + 128 data + 4 right-pad
#define PAIRS  16        // row pairs per tile
#define NTILES 8192      // 1024 planes x 8 row-blocks

__device__ __forceinline__ void do_pair(
    const float* __restrict__ sm0, const float* __restrict__ sm1,
    float* __restrict__ o0, float* __restrict__ o1, int lane,
    float g0, float g1, float g2, float g3)
{
#pragma unroll
    for (int k = 0; k < 2; k++) {
        const int m = lane + 32 * k;  // 0..63
        const float  a0 = sm0[2 * m + 3];
        const float2 b0 = *reinterpret_cast<const float2*>(sm0 + 2 * m + 4);
        const float  e0 = sm0[2 * m + 6];
        const float  a1 = sm1[2 * m + 3];
        const float2 b1 = *reinterpret_cast<const float2*>(sm1 + 2 * m + 4);
        const float  e1 = sm1[2 * m + 6];

        const float cA0 = g0 * b0.x + g2 * a0;    // col 4m
        const float cB0 = g1 * b0.x + g3 * a0;    // col 4m+1
        const float cC0 = g0 * b0.y + g2 * b0.x;  // col 4m+2
        const float cD0 = g1 * b0.y + g3 * b0.x;  // col 4m+3
        const float cE0 = g0 * e0   + g2 * b0.y;  // col 4m+4
        const float cF0 = g1 * e0   + g3 * b0.y;  // col 4m+5
        const float cA1 = g0 * b1.x + g2 * a1;
        const float cB1 = g1 * b1.x + g3 * a1;
        const float cC1 = g0 * b1.y + g2 * b1.x;
        const float cD1 = g1 * b1.y + g3 * b1.x;
        const float cE1 = g0 * e1   + g2 * b1.y;
        const float cF1 = g1 * e1   + g3 * b1.y;

        // Row 2r: cols 4m..4m+3 (dense STG.128, 16B-aligned).
        __stcs(reinterpret_cast<float4*>(o0 + 4 * m),
               make_float4(g0 * cA1 + g2 * cA0, g0 * cB1 + g2 * cB0,
                           g0 * cC1 + g2 * cC0, g0 * cD1 + g2 * cD0));
        // Row 2r+1: cols 4m+2..4m+5 (+8B cancels the 8-mod-16 row offset).
        __stcs(reinterpret_cast<float4*>(o1 + 4 * m + 2),
               make_float4(g1 * cC1 + g3 * cC0, g1 * cD1 + g3 * cD0,
                           g1 * cE1 + g3 * cE0, g1 * cF1 + g3 * cF0));

        if (k == 0 && lane == 0)      // row 2r+1 cols 0,1 (x[-1]=0)
            __stcs(reinterpret_cast<float2*>(o1),
                   make_float2(g1 * cA1 + g3 * cA0, g1 * cB1 + g3 * cB0));
        if (k == 1 && lane == 31)     // row 2r cols 256,257 (x[128]=0)
            __stcs(reinterpret_cast<float2*>(o0 + 256),
                   make_float2(g0 * cE1 + g2 * cE0, g0 * cF1 + g2 * cF0));
    }
}

__global__ void __launch_bounds__(256)
bilinear_up_kernel(const float* __restrict__ x,
                   const float* __restrict__ w,
                   float* __restrict__ out)
{
    __shared__ __align__(16) float tile[2][NROWS * SROW];   // 2 x 9.79 KB

    const int tid  = threadIdx.x;
    const int warp = tid >> 5;
    const int lane = tid & 31;
    const int stride = gridDim.x;
    const float4 z4 = make_float4(0.f, 0.f, 0.f, 0.f);

    // Zero pads of BOTH buffers once (staging never touches words 0-3/132-135).
    for (int i = tid; i < 2 * NROWS * 8; i += 256) {
        const int b   = i / (NROWS * 8);
        const int row = (i >> 3) % NROWS;
        const int wi  = i & 7;
        tile[b][row * SROW + (wi < 4 ? wi : 128 + wi)] = 0.f;
    }

    int t = blockIdx.x;
    // Prolog: stage tile t into buffer 0.
    if (t < NTILES) {
        const int nc = t >> 3, R = (t & 7) * PAIRS;
        const float4* __restrict__ x4 =
            reinterpret_cast<const float4*>(x + (size_t)nc * (HIN * HIN));
#pragma unroll
        for (int u = 0; u < 3; u++) {
            const int i = tid + 256 * u;
            if (i < NROWS * 32) {
                const int row = i >> 5, j = i & 31, g = R - 1 + row;
                const float4 v = (g >= 0 && g < HIN) ? __ldg(&x4[g * 32 + j]) : z4;
                *reinterpret_cast<float4*>(&tile[0][row * SROW + 4 + 4 * j]) = v;
            }
        }
    }
    __syncthreads();

    int cur = 0;
    for (; t < NTILES; t += stride) {
        const int tn = t + stride;

        // Front-issue next tile's LDGs into registers (latency hidden by
        // the compute/store phase below).
        float4 pre0 = z4, pre1 = z4, pre2 = z4;
        if (tn < NTILES) {
            const int ncn = tn >> 3, Rn = (tn & 7) * PAIRS;
            const float4* __restrict__ x4n =
                reinterpret_cast<const float4*>(x + (size_t)ncn * (HIN * HIN));
            {
                const int i = tid;            // < 512 always
                const int row = i >> 5, j = i & 31, g = Rn - 1 + row;
                if (g >= 0 && g < HIN) pre0 = __ldg(&x4n[g * 32 + j]);
            }
            {
                const int i = tid + 256;      // < 512 always
                const int row = i >> 5, j = i & 31, g = Rn - 1 + row;
                if (g >= 0 && g < HIN) pre1 = __ldg(&x4n[g * 32 + j]);
            }
            {
                const int i = tid + 512;      // valid if < 576
                if (i < NROWS * 32) {
                    const int row = i >> 5, j = i & 31, g = Rn - 1 + row;
                    if (g >= 0 && g < HIN) pre2 = __ldg(&x4n[g * 32 + j]);
                }
            }
        }

        // Current tile: filter + compute + direct dense stores.
        const int nc = t >> 3, c = nc & (C - 1), R = (t & 7) * PAIRS;
        const float* __restrict__ wc = w + (size_t)c * (C + 1) * 16;
        const float g1 = sqrtf(__ldg(wc + 5));
        const float g0 = __ldg(wc + 1)  / g1;
        const float g2 = __ldg(wc + 9)  / g1;
        const float g3 = __ldg(wc + 13) / g1;

        float* __restrict__ oplane = out + (size_t)nc * (HOUT * HOUT);
        const float* __restrict__ tb = tile[cur];
#pragma unroll
        for (int p = 0; p < 2; p++) {
            const int tr = warp + 8 * p;
            const int r  = R + tr;
            float* __restrict__ o0 = oplane + (size_t)(2 * r) * HOUT;
            do_pair(tb + tr * SROW, tb + (tr + 1) * SROW,
                    o0, o0 + HOUT, lane, g0, g1, g2, g3);
        }
        // Folded tail pair r=128 (tile row 17 is zeros == "input row 128").
        if ((t & 7) == 7 && warp == 0) {
            float* __restrict__ o0 = oplane + (size_t)(2 * HIN) * HOUT;
            do_pair(tb + 16 * SROW, tb + 17 * SROW,
                    o0, o0 + HOUT, lane, g0, g1, g2, g3);
        }

        // Commit the prefetch into the spare buffer.
        if (tn < NTILES) {
            float* __restrict__ dst = tile[cur ^ 1];
            {
                const int i = tid;
                const int row = i >> 5, j = i & 31;
                *reinterpret_cast<float4*>(&dst[row * SROW + 4 + 4 * j]) = pre0;
            }
            {
                const int i = tid + 256;
                const int row = i >> 5, j = i & 31;
                *reinterpret_cast<float4*>(&dst[row * SROW + 4 + 4 * j]) = pre1;
            }
            {
                const int i = tid + 512;
                if (i < NROWS * 32) {
                    const int row = i >> 5, j = i & 31;
                    *reinterpret_cast<float4*>(&dst[row * SROW + 4 + 4 * j]) = pre2;
                }
            }
        }
        __syncthreads();
        cur ^= 1;
    }
}

extern "C" void kernel_launch(void* const* d_in, const int* in_sizes, int n_in,
                              void* d_out, int out_size)
{
    const float* x = (const float*)d_in[0];   // (4,256,128,128)
    const float* w = (const float*)d_in[1];   // (256,256,4,4)
    float* out = (float*)d_out;               // (4,256,258,258)

    dim3 block(256);
    dim3 grid(1216);                          // persistent: ~8 CTAs/SM target
    bilinear_up_kernel<<<grid, block>>>(x, w, out);
}

// round 14
// speedup vs baseline: 1.0900x; 1.0900x over previous
#include <cuda_runtime.h>
#include <cstdint>

// Bilinear_3882650435896: conv_transpose2d(x, w, stride=2) with block-diagonal
// w (per-channel bilinear filter) == depthwise 2x upsample.
// x: (4,256,128,128) f32 -> out: (4,256,258,258) f32.
//
// R12 -> R14: split the CTA's single 33,024B bulk store into two 16,512B
// copies, the first issued as soon as pairs 0-7 land in smem. The first
// half's drain overlaps the second half's compute; one wait_group 0 at the
// end covers both. Everything else identical to R12 (best so far): smem
// input tile, separable filter, dense STS.128 body, tail pair direct.

#define C     256
#define HIN   128
#define HOUT  258
#define NROWS 18         // input rows staged per block (R-1 .. R+16)
#define SROW  136        // smem row: 4 left-pad + 128 data + 4 right-pad
#define PAIRS 16         // row pairs per block
#define OPAIR (2 * HOUT) // 516 floats per pair
#define HBYTES (8 * OPAIR * 4)       // 16512 B per half (8 pairs)

__device__ __forceinline__ uint32_t smem_u32(const void* p) {
    uint32_t a;
    asm("{ .reg .u64 t; cvta.to.shared.u64 t, %1; cvt.u32.u64 %0, t; }"
        : "=r"(a) : "l"(p));
    return a;
}

// One output row pair from input rows sm0 (r-1) / sm1 (r) into b0/b1.
__device__ __forceinline__ void do_pair(
    const float* __restrict__ sm0, const float* __restrict__ sm1,
    float* __restrict__ b0, float* __restrict__ b1, int lane,
    float g0, float g1, float g2, float g3)
{
#pragma unroll
    for (int k = 0; k < 2; k++) {
        const int m = lane + 32 * k;  // 0..63
        const float  a0 = sm0[2 * m + 3];
        const float2 v0 = *reinterpret_cast<const float2*>(sm0 + 2 * m + 4);
        const float  e0 = sm0[2 * m + 6];
        const float  a1 = sm1[2 * m + 3];
        const float2 v1 = *reinterpret_cast<const float2*>(sm1 + 2 * m + 4);
        const float  e1 = sm1[2 * m + 6];

        const float cA0 = g0 * v0.x + g2 * a0;    // col 4m
        const float cB0 = g1 * v0.x + g3 * a0;    // col 4m+1
        const float cC0 = g0 * v0.y + g2 * v0.x;  // col 4m+2
        const float cD0 = g1 * v0.y + g3 * v0.x;  // col 4m+3
        const float cE0 = g0 * e0   + g2 * v0.y;  // col 4m+4
        const float cF0 = g1 * e0   + g3 * v0.y;  // col 4m+5
        const float cA1 = g0 * v1.x + g2 * a1;
        const float cB1 = g1 * v1.x + g3 * a1;
        const float cC1 = g0 * v1.y + g2 * v1.x;
        const float cD1 = g1 * v1.y + g3 * v1.x;
        const float cE1 = g0 * e1   + g2 * v1.y;
        const float cF1 = g1 * e1   + g3 * v1.y;

        *reinterpret_cast<float4*>(b0 + 4 * m) =
            make_float4(g0 * cA1 + g2 * cA0, g0 * cB1 + g2 * cB0,
                        g0 * cC1 + g2 * cC0, g0 * cD1 + g2 * cD0);
        *reinterpret_cast<float4*>(b1 + 4 * m + 2) =
            make_float4(g1 * cC1 + g3 * cC0, g1 * cD1 + g3 * cD0,
                        g1 * cE1 + g3 * cE0, g1 * cF1 + g3 * cF0);

        if (k == 0 && lane == 0)      // row 2r+1 cols 0,1 (x[-1]=0)
            *reinterpret_cast<float2*>(b1) =
                make_float2(g1 * cA1 + g3 * cA0, g1 * cB1 + g3 * cB0);
        if (k == 1 && lane == 31)     // row 2r cols 256,257 (x[128]=0)
            *reinterpret_cast<float2*>(b0 + 256) =
                make_float2(g0 * cE1 + g2 * cE0, g0 * cF1 + g2 * cF0);
    }
}

__global__ void __launch_bounds__(256)
bilinear_up_kernel(const float* __restrict__ x,
                   const float* __restrict__ w,
                   float* __restrict__ out)
{
    const int nc = blockIdx.y;            // n*C + c
    const int c  = nc & (C - 1);
    const int R  = blockIdx.x * PAIRS;    // first row-pair index, 0..112

    __shared__ __align__(16) float tile[NROWS * SROW];     // 9.79 KB
    __shared__ __align__(16) float obuf[PAIRS * OPAIR];    // 33.0 KB

    // Zero both pads (8 words per row).
    if (threadIdx.x < NROWS * 8) {
        const int row = threadIdx.x >> 3;
        const int wi  = threadIdx.x & 7;
        tile[row * SROW + (wi < 4 ? wi : 128 + wi)] = 0.f;
    }

    // Stage 18 input rows as float4 (OOB rows zero-filled).
    const float4* __restrict__ x4 =
        reinterpret_cast<const float4*>(x + (size_t)nc * (HIN * HIN));
    const float4 z4 = make_float4(0.f, 0.f, 0.f, 0.f);
#pragma unroll
    for (int i = threadIdx.x; i < NROWS * 32; i += 256) {
        const int row = i >> 5;
        const int j   = i & 31;
        const int g   = R - 1 + row;
        const float4 v = (g >= 0 && g < HIN) ? __ldg(&x4[g * 32 + j]) : z4;
        *reinterpret_cast<float4*>(&tile[row * SROW + 4 + 4 * j]) = v;
    }

    // Separable filter: f[kh][kw] = g[kh]*g[kw] (exact for bilinear taps).
    const float* __restrict__ wc = w + (size_t)c * (C + 1) * 16;
    const float g1 = sqrtf(__ldg(wc + 5));
    const float g0 = __ldg(wc + 1)  / g1;
    const float g2 = __ldg(wc + 9)  / g1;
    const float g3 = __ldg(wc + 13) / g1;

    __syncthreads();

    const int warp = threadIdx.x >> 5;
    const int lane = threadIdx.x & 31;
    float* __restrict__ gbase = out + (size_t)nc * (HOUT * HOUT)
                                    + (size_t)R * OPAIR;

    // Half 1: pairs 0..7 -> obuf[0 .. 8*OPAIR).
    {
        float* __restrict__ b0 = &obuf[warp * OPAIR];
        do_pair(&tile[warp * SROW], &tile[(warp + 1) * SROW],
                b0, b0 + HOUT, lane, g0, g1, g2, g3);
    }
    __syncthreads();
    if (threadIdx.x == 0) {
        asm volatile("fence.proxy.async.shared::cta;" ::: "memory");
        asm volatile(
            "cp.async.bulk.global.shared::cta.bulk_group [%0], [%1], %2;"
            :: "l"(gbase), "r"(smem_u32(obuf)), "n"(HBYTES) : "memory");
        asm volatile("cp.async.bulk.commit_group;" ::: "memory");
    }

    // Half 2: pairs 8..15 -> obuf[8*OPAIR ..).
    {
        const int tr = warp + 8;
        float* __restrict__ b0 = &obuf[tr * OPAIR];
        do_pair(&tile[tr * SROW], &tile[(tr + 1) * SROW],
                b0, b0 + HOUT, lane, g0, g1, g2, g3);
    }

    // Tail pair r=128 (output rows 256,257): last block column, warp 0,
    // direct global stores (tile row 17 is zeros == "input row 128").
    if (R == HIN - PAIRS && warp == 0) {
        float* __restrict__ t0 =
            out + (size_t)nc * (HOUT * HOUT) + (size_t)(2 * HIN) * HOUT;
        do_pair(&tile[16 * SROW], &tile[17 * SROW],
                t0, t0 + HOUT, lane, g0, g1, g2, g3);
    }

    __syncthreads();
    if (threadIdx.x == 0) {
        asm volatile("fence.proxy.async.shared::cta;" ::: "memory");
        asm volatile(
            "cp.async.bulk.global.shared::cta.bulk_group [%0], [%1], %2;"
            :: "l"(gbase + 8 * OPAIR), "r"(smem_u32(&obuf[8 * OPAIR])),
               "n"(HBYTES) : "memory");
        asm volatile("cp.async.bulk.commit_group;" ::: "memory");
        asm volatile("cp.async.bulk.wait_group 0;" ::: "memory");
    }
}

extern "C" void kernel_launch(void* const* d_in, const int* in_sizes, int n_in,
                              void* d_out, int out_size)
{
    const float* x = (const float*)d_in[0];   // (4,256,128,128)
    const float* w = (const float*)d_in[1];   // (256,256,4,4)
    float* out = (float*)d_out;               // (4,256,258,258)

    dim3 block(256);
    dim3 grid(HIN / PAIRS, 4 * C);            // (8, 1024)
    bilinear_up_kernel<<<grid, block>>>(x, w, out);
}

// round 15
// speedup vs baseline: 1.0957x; 1.0052x over previous
#include <cuda_runtime.h>

// Bilinear_3882650435896: conv_transpose2d(x, w, stride=2) with block-diagonal
// w (per-channel bilinear filter) == depthwise 2x upsample.
// x: (4,256,128,128) f32 -> out: (4,256,258,258) f32.
//
// R11 -> R15: single-variable store-policy test. Six designs all pin at
// ~5.5TB/s with DRAM ~68% regardless of SM-side structure -> suspect the
// L2 write-back eviction pacing. Swap __stcs (evict-first write-back) for
// __stwt (write-through): DRAM write stream tracks store issue instead of
// L2 eviction. Everything else is R11 verbatim (best direct-store variant:
// occ 90%, regs 32, dense STG.128 both rows, separable filter).

#define C     256
#define HIN   128
#define HOUT  258
#define NROWS 18         // input rows staged per block (R-1 .. R+16)
#define SROW  136        // smem row: 4 left-pad + 128 data + 4 right-pad
#define PAIRS 16         // row pairs per block (plus 1 folded tail pair)

__device__ __forceinline__ void do_pair(
    const float* __restrict__ sm0, const float* __restrict__ sm1,
    float* __restrict__ o0, float* __restrict__ o1, int lane,
    float g0, float g1, float g2, float g3)
{
#pragma unroll
    for (int k = 0; k < 2; k++) {
        const int m = lane + 32 * k;  // 0..63
        const float  a0 = sm0[2 * m + 3];
        const float2 b0 = *reinterpret_cast<const float2*>(sm0 + 2 * m + 4);
        const float  e0 = sm0[2 * m + 6];
        const float  a1 = sm1[2 * m + 3];
        const float2 b1 = *reinterpret_cast<const float2*>(sm1 + 2 * m + 4);
        const float  e1 = sm1[2 * m + 6];

        const float cA0 = g0 * b0.x + g2 * a0;    // col 4m
        const float cB0 = g1 * b0.x + g3 * a0;    // col 4m+1
        const float cC0 = g0 * b0.y + g2 * b0.x;  // col 4m+2
        const float cD0 = g1 * b0.y + g3 * b0.x;  // col 4m+3
        const float cE0 = g0 * e0   + g2 * b0.y;  // col 4m+4
        const float cF0 = g1 * e0   + g3 * b0.y;  // col 4m+5
        const float cA1 = g0 * b1.x + g2 * a1;
        const float cB1 = g1 * b1.x + g3 * a1;
        const float cC1 = g0 * b1.y + g2 * b1.x;
        const float cD1 = g1 * b1.y + g3 * b1.x;
        const float cE1 = g0 * e1   + g2 * b1.y;
        const float cF1 = g1 * e1   + g3 * b1.y;

        // Row 2r: cols 4m..4m+3 (dense STG.128, 16B-aligned, write-through).
        __stwt(reinterpret_cast<float4*>(o0 + 4 * m),
               make_float4(g0 * cA1 + g2 * cA0, g0 * cB1 + g2 * cB0,
                           g0 * cC1 + g2 * cC0, g0 * cD1 + g2 * cD0));
        // Row 2r+1: cols 4m+2..4m+5 (+8B cancels o1's 8-mod-16 offset).
        __stwt(reinterpret_cast<float4*>(o1 + 4 * m + 2),
               make_float4(g1 * cC1 + g3 * cC0, g1 * cD1 + g3 * cD0,
                           g1 * cE1 + g3 * cE0, g1 * cF1 + g3 * cF0));

        if (k == 0 && lane == 0)      // row 2r+1 cols 0,1 (x[-1]=0)
            __stwt(reinterpret_cast<float2*>(o1),
                   make_float2(g1 * cA1 + g3 * cA0, g1 * cB1 + g3 * cB0));
        if (k == 1 && lane == 31)     // row 2r cols 256,257 (x[128]=0)
            __stwt(reinterpret_cast<float2*>(o0 + 256),
                   make_float2(g0 * cE1 + g2 * cE0, g0 * cF1 + g2 * cF0));
    }
}

__global__ void __launch_bounds__(256)
bilinear_up_kernel(const float* __restrict__ x,
                   const float* __restrict__ w,
                   float* __restrict__ out)
{
    const int nc = blockIdx.y;            // n*C + c
    const int c  = nc & (C - 1);
    const int R  = blockIdx.x * PAIRS;    // first row-pair index, 0..112

    __shared__ __align__(16) float tile[NROWS * SROW];   // 9.56 KB

    // Zero both pads (8 words per row): x[-1] -> tile[.][3], x[128] -> [132].
    if (threadIdx.x < NROWS * 8) {
        const int row = threadIdx.x >> 3;
        const int wi  = threadIdx.x & 7;
        tile[row * SROW + (wi < 4 ? wi : 128 + wi)] = 0.f;
    }

    // Stage 18 input rows as float4 (OOB rows zero-filled).
    const float4* __restrict__ x4 =
        reinterpret_cast<const float4*>(x + (size_t)nc * (HIN * HIN));
    const float4 z4 = make_float4(0.f, 0.f, 0.f, 0.f);
#pragma unroll
    for (int i = threadIdx.x; i < NROWS * 32; i += 256) {
        const int row = i >> 5;
        const int j   = i & 31;
        const int g   = R - 1 + row;
        const float4 v = (g >= 0 && g < HIN) ? __ldg(&x4[g * 32 + j]) : z4;
        *reinterpret_cast<float4*>(&tile[row * SROW + 4 + 4 * j]) = v;
    }

    // Separable filter: f[kh][kw] = g[kh]*g[kw] (exact for bilinear taps).
    const float* __restrict__ wc = w + (size_t)c * (C + 1) * 16;
    const float g1 = sqrtf(__ldg(wc + 5));     // f[1][1]
    const float g0 = __ldg(wc + 1)  / g1;      // f[0][1]
    const float g2 = __ldg(wc + 9)  / g1;      // f[2][1]
    const float g3 = __ldg(wc + 13) / g1;      // f[3][1]

    __syncthreads();

    const int warp = threadIdx.x >> 5;
    const int lane = threadIdx.x & 31;
    float* __restrict__ oplane = out + (size_t)nc * (HOUT * HOUT);

#pragma unroll
    for (int p = 0; p < 2; p++) {
        const int tr = warp + 8 * p;      // tile row of input row r-1
        const int r  = R + tr;            // row-pair index, always <= 127
        float* __restrict__ o0 = oplane + (size_t)(2 * r) * HOUT;
        do_pair(&tile[tr * SROW], &tile[(tr + 1) * SROW],
                o0, o0 + HOUT, lane, g0, g1, g2, g3);
    }

    // Folded tail pair r = 128 (output rows 256,257): last block only,
    // warp 0, tile rows 16 (input row 127) and 17 (zeros == "row 128").
    if (R == HIN - PAIRS && warp == 0) {
        float* __restrict__ o0 = oplane + (size_t)(2 * HIN) * HOUT;
        do_pair(&tile[16 * SROW], &tile[17 * SROW],
                o0, o0 + HOUT, lane, g0, g1, g2, g3);
    }
}

extern "C" void kernel_launch(void* const* d_in, const int* in_sizes, int n_in,
                              void* d_out, int out_size)
{
    const float* x = (const float*)d_in[0];   // (4,256,128,128)
    const float* w = (const float*)d_in[1];   // (256,256,4,4)
    float* out = (float*)d_out;               // (4,256,258,258)

    dim3 block(256);
    dim3 grid(HIN / PAIRS, 4 * C);            // (8, 1024)
    bilinear_up_kernel<<<grid, block>>>(x, w, out);
}

// round 16
// speedup vs baseline: 1.0963x; 1.0006x over previous
#include <cuda_runtime.h>
#include <cstdint>

// Bilinear_3882650435896: conv_transpose2d(x, w, stride=2) with block-diagonal
// w (per-channel bilinear filter) == depthwise 2x upsample.
// x: (4,256,128,128) f32 -> out: (4,256,258,258) f32.
//
// R15 -> R16 (final refinement at the DRAM write wall): stage the input tile
// via cp.async.cg (LDGSTS, global->shared direct, src-size=0 zero-fill for
// OOB rows) instead of LDG+STS, shortening the CTA's pre-store latency
// exposure. Everything else is R15 verbatim: warp per row pair, dense
// STG.128 on both output rows (lane stride == store width), __stwt,
// separable filter, occ-8 / 32-reg shape.

#define C     256
#define HIN   128
#define HOUT  258
#define NROWS 18         // input rows staged per block (R-1 .. R+16)
#define SROW  136        // smem row: 4 left-pad + 128 data + 4 right-pad
#define PAIRS 16         // row pairs per block (plus 1 folded tail pair)

__device__ __forceinline__ uint32_t smem_u32(const void* p) {
    uint32_t a;
    asm("{ .reg .u64 t; cvta.to.shared.u64 t, %1; cvt.u32.u64 %0, t; }"
        : "=r"(a) : "l"(p));
    return a;
}

__device__ __forceinline__ void do_pair(
    const float* __restrict__ sm0, const float* __restrict__ sm1,
    float* __restrict__ o0, float* __restrict__ o1, int lane,
    float g0, float g1, float g2, float g3)
{
#pragma unroll
    for (int k = 0; k < 2; k++) {
        const int m = lane + 32 * k;  // 0..63
        const float  a0 = sm0[2 * m + 3];
        const float2 b0 = *reinterpret_cast<const float2*>(sm0 + 2 * m + 4);
        const float  e0 = sm0[2 * m + 6];
        const float  a1 = sm1[2 * m + 3];
        const float2 b1 = *reinterpret_cast<const float2*>(sm1 + 2 * m + 4);
        const float  e1 = sm1[2 * m + 6];

        const float cA0 = g0 * b0.x + g2 * a0;    // col 4m
        const float cB0 = g1 * b0.x + g3 * a0;    // col 4m+1
        const float cC0 = g0 * b0.y + g2 * b0.x;  // col 4m+2
        const float cD0 = g1 * b0.y + g3 * b0.x;  // col 4m+3
        const float cE0 = g0 * e0   + g2 * b0.y;  // col 4m+4
        const float cF0 = g1 * e0   + g3 * b0.y;  // col 4m+5
        const float cA1 = g0 * b1.x + g2 * a1;
        const float cB1 = g1 * b1.x + g3 * a1;
        const float cC1 = g0 * b1.y + g2 * b1.x;
        const float cD1 = g1 * b1.y + g3 * b1.x;
        const float cE1 = g0 * e1   + g2 * b1.y;
        const float cF1 = g1 * e1   + g3 * b1.y;

        // Row 2r: cols 4m..4m+3 (dense STG.128, 16B-aligned).
        __stwt(reinterpret_cast<float4*>(o0 + 4 * m),
               make_float4(g0 * cA1 + g2 * cA0, g0 * cB1 + g2 * cB0,
                           g0 * cC1 + g2 * cC0, g0 * cD1 + g2 * cD0));
        // Row 2r+1: cols 4m+2..4m+5 (+8B cancels o1's 8-mod-16 offset).
        __stwt(reinterpret_cast<float4*>(o1 + 4 * m + 2),
               make_float4(g1 * cC1 + g3 * cC0, g1 * cD1 + g3 * cD0,
                           g1 * cE1 + g3 * cE0, g1 * cF1 + g3 * cF0));

        if (k == 0 && lane == 0)      // row 2r+1 cols 0,1 (x[-1]=0)
            __stwt(reinterpret_cast<float2*>(o1),
                   make_float2(g1 * cA1 + g3 * cA0, g1 * cB1 + g3 * cB0));
        if (k == 1 && lane == 31)     // row 2r cols 256,257 (x[128]=0)
            __stwt(reinterpret_cast<float2*>(o0 + 256),
                   make_float2(g0 * cE1 + g2 * cE0, g0 * cF1 + g2 * cF0));
    }
}

__global__ void __launch_bounds__(256)
bilinear_up_kernel(const float* __restrict__ x,
                   const float* __restrict__ w,
                   float* __restrict__ out)
{
    const int nc = blockIdx.y;            // n*C + c
    const int c  = nc & (C - 1);
    const int R  = blockIdx.x * PAIRS;    // first row-pair index, 0..112

    __shared__ __align__(16) float tile[NROWS * SROW];   // 9.56 KB

    // Zero both pads (8 words per row): x[-1] -> tile[.][3], x[128] -> [132].
    if (threadIdx.x < NROWS * 8) {
        const int row = threadIdx.x >> 3;
        const int wi  = threadIdx.x & 7;
        tile[row * SROW + (wi < 4 ? wi : 128 + wi)] = 0.f;
    }

    // Stage 18 input rows via cp.async.cg (global->shared direct, 16B each;
    // OOB rows use src-size=0 => zero-fill). 576 vectors / 256 threads.
    const float4* __restrict__ x4 =
        reinterpret_cast<const float4*>(x + (size_t)nc * (HIN * HIN));
#pragma unroll
    for (int u = 0; u < 3; u++) {
        const int i = threadIdx.x + 256 * u;
        if (i < NROWS * 32) {
            const int row = i >> 5;
            const int j   = i & 31;
            const int g   = R - 1 + row;
            const bool valid = (g >= 0 && g < HIN);
            const float4* src = x4 + (valid ? g * 32 + j : 0);  // clamp OOB
            const uint32_t dst = smem_u32(&tile[row * SROW + 4 + 4 * j]);
            const int srcsize = valid ? 16 : 0;
            asm volatile(
                "cp.async.cg.shared.global [%0], [%1], 16, %2;"
                :: "r"(dst), "l"(src), "r"(srcsize) : "memory");
        }
    }
    asm volatile("cp.async.commit_group;" ::: "memory");

    // Separable filter: f[kh][kw] = g[kh]*g[kw] (exact for bilinear taps).
    // Issued while the async copies are in flight.
    const float* __restrict__ wc = w + (size_t)c * (C + 1) * 16;
    const float g1 = sqrtf(__ldg(wc + 5));     // f[1][1]
    const float g0 = __ldg(wc + 1)  / g1;      // f[0][1]
    const float g2 = __ldg(wc + 9)  / g1;      // f[2][1]
    const float g3 = __ldg(wc + 13) / g1;      // f[3][1]

    asm volatile("cp.async.wait_group 0;" ::: "memory");
    __syncthreads();

    const int warp = threadIdx.x >> 5;
    const int lane = threadIdx.x & 31;
    float* __restrict__ oplane = out + (size_t)nc * (HOUT * HOUT);

#pragma unroll
    for (int p = 0; p < 2; p++) {
        const int tr = warp + 8 * p;      // tile row of input row r-1
        const int r  = R + tr;            // row-pair index, always <= 127
        float* __restrict__ o0 = oplane + (size_t)(2 * r) * HOUT;
        do_pair(&tile[tr * SROW], &tile[(tr + 1) * SROW],
                o0, o0 + HOUT, lane, g0, g1, g2, g3);
    }

    // Folded tail pair r = 128 (output rows 256,257): last block only,
    // warp 0, tile rows 16 (input row 127) and 17 (zeros == "row 128").
    if (R == HIN - PAIRS && warp == 0) {
        float* __restrict__ o0 = oplane + (size_t)(2 * HIN) * HOUT;
        do_pair(&tile[16 * SROW], &tile[17 * SROW],
                o0, o0 + HOUT, lane, g0, g1, g2, g3);
    }
}

extern "C" void kernel_launch(void* const* d_in, const int* in_sizes, int n_in,
                              void* d_out, int out_size)
{
    const float* x = (const float*)d_in[0];   // (4,256,128,128)
    const float* w = (const float*)d_in[1];   // (256,256,4,4)
    float* out = (float*)d_out;               // (4,256,258,258)

    dim3 block(256);
    dim3 grid(HIN / PAIRS, 4 * C);            // (8, 1024)
    bilinear_up_kernel<<<grid, block>>>(x, w, out);
}